// round 3
// baseline (speedup 1.0000x reference)
#include <cuda_runtime.h>
#include <math.h>

// Problem constants
#define BATCH   32768
#define NAG     6
#define L_IN    225
#define D_ENC   128
#define AD      64
#define OUTC    5

// Tiling
#define NB      8           // batches per CTA
#define ROWS    (NB*NAG)    // 48 encoder rows per CTA
#define KT      16
#define THREADS 256
#define A_PAD   49          // As row stride (16 distinct banks for kk*49)

typedef unsigned long long ull;

// Precomputed folded weights (device scratch; 16B aligned for vector loads)
__device__ __align__(16) float g_M[D_ENC * D_ENC];   // q_w @ k_w^T
__device__ __align__(16) float g_Wt[30 * D_ENC];     // fc weights, [(pos*5+o)][k]

__device__ __forceinline__ ull pack2(float x) {
    ull r; asm("mov.b64 %0, {%1, %1};" : "=l"(r) : "f"(x)); return r;
}
__device__ __forceinline__ void fma2(ull &c, ull a, ull b) {
    asm("fma.rn.f32x2 %0, %1, %2, %0;" : "+l"(c) : "l"(a), "l"(b));
}
__device__ __forceinline__ float2 unpack2(ull v) {
    float2 f; asm("mov.b64 {%0, %1}, %2;" : "=f"(f.x), "=f"(f.y) : "l"(v)); return f;
}

__global__ void precompute_kernel(const float* __restrict__ q_w,
                                  const float* __restrict__ k_w,
                                  const float* __restrict__ fc_w) {
    int i = blockIdx.x;    // 0..127
    int j = threadIdx.x;   // 0..127
    float s = 0.f;
    #pragma unroll 8
    for (int a = 0; a < AD; ++a) s += q_w[i * AD + a] * k_w[j * AD + a];
    g_M[i * D_ENC + j] = s;
    if (j < 30) {
        int pos = j / 5, o = j % 5;
        float v;
        if (pos == 0) {
            v = 0.f;
            #pragma unroll
            for (int e = 0; e < 5; ++e) v += fc_w[(e * D_ENC + i) * OUTC + o];
        } else {
            v = fc_w[((pos + 4) * D_ENC + i) * OUTC + o];
        }
        g_Wt[j * D_ENC + i] = v;
    }
}

// Shared memory layout (floats):
#define OFF_AS  0                         // KT * 49   = 784
#define OFF_BS  (OFF_AS + KT*A_PAD)       // 16 * 128  = 2048
#define OFF_ES  (OFF_BS + KT*D_ENC)       // 48 * 132  = 6336
#define OFF_TS  (OFF_ES + ROWS*132)       // 8 * 132   = 1056
#define OFF_SAL (OFF_TS + NB*132)         // 8 * 5     = 40
#define OFF_RL  (OFF_SAL + NB*5)          // 48 * 5    = 240
#define SMEM_FLOATS (OFF_RL + ROWS*5)     // 10504 floats = 42016 bytes (< 48KB)

__global__ __launch_bounds__(THREADS, 3)
void policy_fused_kernel(const float* __restrict__ obs,
                         const float* __restrict__ enc_w,
                         const float* __restrict__ enc_b,
                         const float* __restrict__ fc_b,
                         const float* __restrict__ u,
                         float* __restrict__ out) {
    extern __shared__ float sm[];
    float* As  = sm + OFF_AS;
    float* Bs  = sm + OFF_BS;
    float* Es  = sm + OFF_ES;
    float* Ts  = sm + OFF_TS;
    float* Sal = sm + OFF_SAL;
    float* RL  = sm + OFF_RL;

    const int tid  = threadIdx.x;
    const int tn   = tid & 15;   // 16 column threads (8 cols each)
    const int tm   = tid >> 4;   // 16 row threads (3 rows each)
    const int wid  = tid >> 5;   // warp id (0..7)
    const int lane = tid & 31;

    // ---- Phase 1: E = relu(obs_rows @ enc_w + enc_b), 48x128, K=225 ----
    ull acc[3][4];
    #pragma unroll
    for (int r = 0; r < 3; ++r)
        #pragma unroll
        for (int j = 0; j < 4; ++j) acc[r][j] = 0ull;

    const float* obsBase = obs + (size_t)blockIdx.x * NB * NAG * L_IN;

    for (int k0 = 0; k0 < L_IN; k0 += KT) {
        // A tile: 48 rows x KT k, transposed [k][row]
        #pragma unroll
        for (int t = 0; t < 3; ++t) {
            int idx = tid + THREADS * t;     // < 768
            int r  = idx >> 4;
            int kk = idx & 15;
            int kg = k0 + kk;
            As[kk * A_PAD + r] = (kg < L_IN) ? obsBase[r * L_IN + kg] : 0.f;
        }
        // B tile: KT x 128 via float4
        #pragma unroll
        for (int t = 0; t < 2; ++t) {
            int fi = tid + THREADS * t;      // < 512 float4s
            int kk = fi >> 5;
            int n4 = (fi & 31) * 4;
            int kg = k0 + kk;
            float4 v = make_float4(0.f, 0.f, 0.f, 0.f);
            if (kg < L_IN) v = *reinterpret_cast<const float4*>(&enc_w[kg * D_ENC + n4]);
            *reinterpret_cast<float4*>(&Bs[kk * D_ENC + n4]) = v;
        }
        __syncthreads();

        #pragma unroll
        for (int kk = 0; kk < KT; ++kk) {
            const ull* bp = reinterpret_cast<const ull*>(&Bs[kk * D_ENC + tn * 8]);
            ull b0 = bp[0], b1 = bp[1], b2 = bp[2], b3 = bp[3];
            #pragma unroll
            for (int r = 0; r < 3; ++r) {
                ull av = pack2(As[kk * A_PAD + tm * 3 + r]);
                fma2(acc[r][0], av, b0);
                fma2(acc[r][1], av, b1);
                fma2(acc[r][2], av, b2);
                fma2(acc[r][3], av, b3);
            }
        }
        __syncthreads();
    }

    // Epilogue: bias + relu -> Es
    {
        float4 bb0 = *reinterpret_cast<const float4*>(&enc_b[tn * 8]);
        float4 bb1 = *reinterpret_cast<const float4*>(&enc_b[tn * 8 + 4]);
        float bias[8] = {bb0.x, bb0.y, bb0.z, bb0.w, bb1.x, bb1.y, bb1.z, bb1.w};
        #pragma unroll
        for (int r = 0; r < 3; ++r) {
            float* erow = &Es[(tm * 3 + r) * 132 + tn * 8];
            #pragma unroll
            for (int j = 0; j < 4; ++j) {
                float2 f = unpack2(acc[r][j]);
                erow[2*j]   = fmaxf(f.x + bias[2*j],   0.f);
                erow[2*j+1] = fmaxf(f.y + bias[2*j+1], 0.f);
            }
        }
    }
    __syncthreads();

    // ---- Phase 2: T = E0 @ M (8x128, K=128), scaled by 1/sqrt(64)=1/8 ----
    {
        const int tb = tid >> 5;   // batch 0..7
        const int tc = tid & 31;   // col group (4 cols = 2 ulls)
        ull acc2[2] = {0ull, 0ull};
        for (int k0 = 0; k0 < D_ENC; k0 += KT) {
            #pragma unroll
            for (int t = 0; t < 2; ++t) {
                int fi = tid + THREADS * t;
                int kk = fi >> 5;
                int n4 = (fi & 31) * 4;
                *reinterpret_cast<float4*>(&Bs[kk * D_ENC + n4]) =
                    *reinterpret_cast<const float4*>(&g_M[(k0 + kk) * D_ENC + n4]);
            }
            __syncthreads();
            #pragma unroll
            for (int kk = 0; kk < KT; ++kk) {
                ull av = pack2(Es[(tb * 6) * 132 + k0 + kk]);  // agent row of batch tb
                const ull* bp = reinterpret_cast<const ull*>(&Bs[kk * D_ENC + tc * 4]);
                fma2(acc2[0], av, bp[0]);
                fma2(acc2[1], av, bp[1]);
            }
            __syncthreads();
        }
        float* trow = &Ts[tb * 132 + tc * 4];
        float2 f0 = unpack2(acc2[0]);
        float2 f1 = unpack2(acc2[1]);
        trow[0] = f0.x * 0.125f;
        trow[1] = f0.y * 0.125f;
        trow[2] = f1.x * 0.125f;
        trow[3] = f1.y * 0.125f;
    }
    __syncthreads();

    // ---- Phase 3: scores_j = T[b] . E[vis_j], softmax over 5 (warp per batch) ----
    {
        int b = wid;
        float part[5] = {0.f, 0.f, 0.f, 0.f, 0.f};
        #pragma unroll
        for (int c = 0; c < 4; ++c) {
            int kk = c * 32 + lane;
            float tv = Ts[b * 132 + kk];
            #pragma unroll
            for (int j = 0; j < 5; ++j)
                part[j] += tv * Es[(b * 6 + 1 + j) * 132 + kk];
        }
        #pragma unroll
        for (int off = 16; off > 0; off >>= 1)
            #pragma unroll
            for (int j = 0; j < 5; ++j)
                part[j] += __shfl_down_sync(0xffffffffu, part[j], off);
        if (lane == 0) {
            float m = part[0];
            #pragma unroll
            for (int j = 1; j < 5; ++j) m = fmaxf(m, part[j]);
            float ex[5], s = 0.f;
            #pragma unroll
            for (int j = 0; j < 5; ++j) { ex[j] = expf(part[j] - m); s += ex[j]; }
            float inv = 1.f / s;
            #pragma unroll
            for (int j = 0; j < 5; ++j) Sal[b * 5 + j] = ex[j] * inv;
        }
    }

    // ---- Phase 4: per-row fc logits  RL[r][o] = E[r] . W[pos(r)*5+o] ----
    // Warp w handles weight rows po = w, w+8, w+16, w+24 (register-cached).
    for (int po = wid; po < 30; po += 8) {
        int pos = po / 5, o = po % 5;
        float wreg[4];
        #pragma unroll
        for (int c = 0; c < 4; ++c) wreg[c] = g_Wt[po * D_ENC + c * 32 + lane];
        #pragma unroll
        for (int i = 0; i < NB; ++i) {
            int r = i * 6 + pos;
            float p = 0.f;
            #pragma unroll
            for (int c = 0; c < 4; ++c)
                p += Es[r * 132 + c * 32 + lane] * wreg[c];
            #pragma unroll
            for (int off = 16; off > 0; off >>= 1)
                p += __shfl_down_sync(0xffffffffu, p, off);
            if (lane == 0) RL[r * 5 + o] = p;
        }
    }
    __syncthreads();

    // ---- Phase 5: combine + gumbel + argmax (order-preserving: skip softmax/TAU) ----
    if (tid < NB) {
        int b = tid;
        int gb = blockIdx.x * NB + b;
        float best = -1e38f;
        int bi = 0;
        #pragma unroll
        for (int o = 0; o < OUTC; ++o) {
            float l = RL[(b * 6) * 5 + o] + fc_b[o];
            #pragma unroll
            for (int j = 0; j < 5; ++j)
                l += Sal[b * 5 + j] * RL[(b * 6 + 1 + j) * 5 + o];
            float uu = u[gb * OUTC + o];
            float g = -logf(-logf(uu + 1e-10f) + 1e-10f);
            l += g;
            if (l > best) { best = l; bi = o; }
        }
        out[gb] = (float)bi;   // __output__ is float32 (round-1 evidence)
    }
}

extern "C" void kernel_launch(void* const* d_in, const int* in_sizes, int n_in,
                              void* d_out, int out_size) {
    const float* obs   = (const float*)d_in[0];
    const float* enc_w = (const float*)d_in[1];
    const float* enc_b = (const float*)d_in[2];
    const float* q_w   = (const float*)d_in[3];
    const float* k_w   = (const float*)d_in[4];
    const float* fc_w  = (const float*)d_in[5];
    const float* fc_b  = (const float*)d_in[6];
    const float* u     = (const float*)d_in[7];
    float* out = (float*)d_out;

    precompute_kernel<<<D_ENC, D_ENC>>>(q_w, k_w, fc_w);

    int grid = BATCH / NB;  // 4096
    policy_fused_kernel<<<grid, THREADS, SMEM_FLOATS * sizeof(float)>>>(
        obs, enc_w, enc_b, fc_b, u, out);
}

// round 5
// speedup vs baseline: 1.4742x; 1.4742x over previous
#include <cuda_runtime.h>
#include <math.h>

// Problem constants
#define BATCH   32768
#define NAG     6
#define L_IN    225
#define D_ENC   128
#define AD      64
#define OUTC    5

// Tiling
#define NB      8            // batches per CTA
#define ROWS    (NB*NAG)     // 48 encoder rows per CTA
#define KT      16
#define NTILES  15           // 15*16 = 240 >= 225 (zero-padded tail)
#define THREADS 256
#define A_STRIDE 20          // As row stride ([row][k]), multiple of 4 for float4

typedef unsigned long long ull;

// Precomputed folded weights (device scratch; 16B aligned for vector loads)
__device__ __align__(16) float g_M[D_ENC * D_ENC];   // q_w @ k_w^T
__device__ __align__(16) float g_Wt[30 * D_ENC];     // fc weights, [(pos*5+o)][k]

__device__ __forceinline__ ull pack2(float x) {
    ull r; asm("mov.b64 %0, {%1, %1};" : "=l"(r) : "f"(x)); return r;
}
__device__ __forceinline__ void fma2(ull &c, ull a, ull b) {
    asm("fma.rn.f32x2 %0, %1, %2, %0;" : "+l"(c) : "l"(a), "l"(b));
}
__device__ __forceinline__ float2 unpack2(ull v) {
    float2 f; asm("mov.b64 {%0, %1}, %2;" : "=f"(f.x), "=f"(f.y) : "l"(v)); return f;
}

__global__ void precompute_kernel(const float* __restrict__ q_w,
                                  const float* __restrict__ k_w,
                                  const float* __restrict__ fc_w) {
    int i = blockIdx.x;    // 0..127
    int j = threadIdx.x;   // 0..127
    float s = 0.f;
    #pragma unroll 8
    for (int a = 0; a < AD; ++a) s += q_w[i * AD + a] * k_w[j * AD + a];
    g_M[i * D_ENC + j] = s;
    if (j < 30) {
        int pos = j / 5, o = j % 5;
        float v;
        if (pos == 0) {
            v = 0.f;
            #pragma unroll
            for (int e = 0; e < 5; ++e) v += fc_w[(e * D_ENC + i) * OUTC + o];
        } else {
            v = fc_w[((pos + 4) * D_ENC + i) * OUTC + o];
        }
        g_Wt[j * D_ENC + i] = v;
    }
}

// Shared memory layout (floats):
#define AS_BUF   (ROWS*A_STRIDE)            // 960 per buffer
#define BS_BUF   (KT*D_ENC)                 // 2048 per buffer
#define OFF_AS   0                          // 2 * 960  = 1920
#define OFF_BS   (OFF_AS + 2*AS_BUF)        // 2 * 2048 = 4096
#define OFF_ES   (OFF_BS + 2*BS_BUF)        // 48 * 132 = 6336
#define OFF_TS   (OFF_ES + ROWS*132)        // 8 * 132  = 1056
#define OFF_SAL  (OFF_TS + NB*132)          // 40
#define OFF_RL   (OFF_SAL + NB*5)           // 240
#define SMEM_FLOATS (OFF_RL + ROWS*5)       // 13688 floats = 54752 B (needs opt-in)

__global__ __launch_bounds__(THREADS, 2)
void policy_fused_kernel(const float* __restrict__ obs,
                         const float* __restrict__ enc_w,
                         const float* __restrict__ enc_b,
                         const float* __restrict__ fc_b,
                         const float* __restrict__ u,
                         float* __restrict__ out) {
    extern __shared__ float sm[];
    float* Es  = sm + OFF_ES;
    float* Ts  = sm + OFF_TS;
    float* Sal = sm + OFF_SAL;
    float* RL  = sm + OFF_RL;

    const int tid  = threadIdx.x;
    const int wid  = tid >> 5;   // warp id (0..7)
    const int lane = tid & 31;
    const int r0   = wid * 6;    // this warp's 6 encoder rows

    // Per-thread tile-load indices (constant across tiles)
    const int la_r[3]  = { tid >> 4, (tid + 256) >> 4, (tid + 512) >> 4 };
    const int la_k     = tid & 15;
    const int lb_kk[2] = { tid >> 5, (tid + 256) >> 5 };
    const int lb_n4    = (tid & 31) * 4;

    const float* obsBase = obs + (size_t)blockIdx.x * NB * NAG * L_IN;

    // ---- Phase 1: E = relu(obs_rows @ enc_w + enc_b), 48x128, K=225 ----
    ull acc[6][2];
    #pragma unroll
    for (int r = 0; r < 6; ++r) { acc[r][0] = 0ull; acc[r][1] = 0ull; }

    float  a_pre[3];
    float4 b_pre[2];

    // prefetch + store tile 0
    {
        int kg = la_k;   // k0 = 0
        #pragma unroll
        for (int t = 0; t < 3; ++t) a_pre[t] = obsBase[la_r[t] * L_IN + kg];
        #pragma unroll
        for (int t = 0; t < 2; ++t)
            b_pre[t] = *reinterpret_cast<const float4*>(&enc_w[lb_kk[t] * D_ENC + lb_n4]);
        float* As0 = sm + OFF_AS;
        float* Bs0 = sm + OFF_BS;
        #pragma unroll
        for (int t = 0; t < 3; ++t) As0[la_r[t] * A_STRIDE + la_k] = a_pre[t];
        #pragma unroll
        for (int t = 0; t < 2; ++t)
            *reinterpret_cast<float4*>(&Bs0[lb_kk[t] * D_ENC + lb_n4]) = b_pre[t];
    }
    __syncthreads();

    for (int tile = 0; tile < NTILES; ++tile) {
        const int cur = tile & 1;
        float* Asc = sm + OFF_AS + cur * AS_BUF;
        float* Bsc = sm + OFF_BS + cur * BS_BUF;

        // issue next tile's global loads early (latency hidden under compute)
        if (tile + 1 < NTILES) {
            int k0n = (tile + 1) * KT;
            int kg = k0n + la_k;
            #pragma unroll
            for (int t = 0; t < 3; ++t)
                a_pre[t] = (kg < L_IN) ? obsBase[la_r[t] * L_IN + kg] : 0.f;
            #pragma unroll
            for (int t = 0; t < 2; ++t) {
                int kb = k0n + lb_kk[t];
                b_pre[t] = (kb < L_IN)
                    ? *reinterpret_cast<const float4*>(&enc_w[kb * D_ENC + lb_n4])
                    : make_float4(0.f, 0.f, 0.f, 0.f);
            }
        }

        // compute current tile: 16 kk, thread tile 6 rows x 4 cols
        #pragma unroll
        for (int c4 = 0; c4 < 4; ++c4) {
            float4 a4[6];
            #pragma unroll
            for (int r = 0; r < 6; ++r)
                a4[r] = *reinterpret_cast<const float4*>(&Asc[(r0 + r) * A_STRIDE + c4 * 4]);
            #pragma unroll
            for (int kk = 0; kk < 4; ++kk) {
                const ull* bp = reinterpret_cast<const ull*>(&Bsc[(c4 * 4 + kk) * D_ENC + lane * 4]);
                ull bv0 = bp[0], bv1 = bp[1];
                #pragma unroll
                for (int r = 0; r < 6; ++r) {
                    float av = reinterpret_cast<const float*>(&a4[r])[kk];
                    ull a2 = pack2(av);
                    fma2(acc[r][0], a2, bv0);
                    fma2(acc[r][1], a2, bv1);
                }
            }
        }

        // store prefetched tile into the other buffer
        if (tile + 1 < NTILES) {
            float* Asn = sm + OFF_AS + (1 - cur) * AS_BUF;
            float* Bsn = sm + OFF_BS + (1 - cur) * BS_BUF;
            #pragma unroll
            for (int t = 0; t < 3; ++t) Asn[la_r[t] * A_STRIDE + la_k] = a_pre[t];
            #pragma unroll
            for (int t = 0; t < 2; ++t)
                *reinterpret_cast<float4*>(&Bsn[lb_kk[t] * D_ENC + lb_n4]) = b_pre[t];
        }
        __syncthreads();
    }

    // Epilogue: bias + relu -> Es (float4, conflict-free)
    {
        float4 bb = *reinterpret_cast<const float4*>(&enc_b[lane * 4]);
        #pragma unroll
        for (int r = 0; r < 6; ++r) {
            float2 f0 = unpack2(acc[r][0]);
            float2 f1 = unpack2(acc[r][1]);
            float4 o;
            o.x = fmaxf(f0.x + bb.x, 0.f);
            o.y = fmaxf(f0.y + bb.y, 0.f);
            o.z = fmaxf(f1.x + bb.z, 0.f);
            o.w = fmaxf(f1.y + bb.w, 0.f);
            *reinterpret_cast<float4*>(&Es[(r0 + r) * 132 + lane * 4]) = o;
        }
    }
    __syncthreads();

    // ---- Phase 2: T = E0 @ M (8x128, K=128), scaled by 1/sqrt(64)=1/8 ----
    {
        float* Bs0 = sm + OFF_BS;
        const int tb = wid;        // batch 0..7
        ull acc2[2] = {0ull, 0ull};
        for (int k0 = 0; k0 < D_ENC; k0 += KT) {
            #pragma unroll
            for (int t = 0; t < 2; ++t) {
                int fi = tid + THREADS * t;
                int kk = fi >> 5;
                int n4 = (fi & 31) * 4;
                *reinterpret_cast<float4*>(&Bs0[kk * D_ENC + n4]) =
                    *reinterpret_cast<const float4*>(&g_M[(k0 + kk) * D_ENC + n4]);
            }
            __syncthreads();
            #pragma unroll
            for (int kk = 0; kk < KT; ++kk) {
                ull av = pack2(Es[(tb * 6) * 132 + k0 + kk]);  // agent row of batch tb
                const ull* bp = reinterpret_cast<const ull*>(&Bs0[kk * D_ENC + lane * 4]);
                fma2(acc2[0], av, bp[0]);
                fma2(acc2[1], av, bp[1]);
            }
            __syncthreads();
        }
        float* trow = &Ts[tb * 132 + lane * 4];
        float2 f0 = unpack2(acc2[0]);
        float2 f1 = unpack2(acc2[1]);
        float4 o; o.x = f0.x * 0.125f; o.y = f0.y * 0.125f;
        o.z = f1.x * 0.125f; o.w = f1.y * 0.125f;
        *reinterpret_cast<float4*>(trow) = o;
    }
    __syncthreads();

    // ---- Phase 3: scores_j = T[b] . E[vis_j], softmax over 5 (warp per batch) ----
    {
        int b = wid;
        float part[5] = {0.f, 0.f, 0.f, 0.f, 0.f};
        #pragma unroll
        for (int c = 0; c < 4; ++c) {
            int kk = c * 32 + lane;
            float tv = Ts[b * 132 + kk];
            #pragma unroll
            for (int j = 0; j < 5; ++j)
                part[j] += tv * Es[(b * 6 + 1 + j) * 132 + kk];
        }
        #pragma unroll
        for (int off = 16; off > 0; off >>= 1)
            #pragma unroll
            for (int j = 0; j < 5; ++j)
                part[j] += __shfl_down_sync(0xffffffffu, part[j], off);
        if (lane == 0) {
            float m = part[0];
            #pragma unroll
            for (int j = 1; j < 5; ++j) m = fmaxf(m, part[j]);
            float ex[5], s = 0.f;
            #pragma unroll
            for (int j = 0; j < 5; ++j) { ex[j] = expf(part[j] - m); s += ex[j]; }
            float inv = 1.f / s;
            #pragma unroll
            for (int j = 0; j < 5; ++j) Sal[b * 5 + j] = ex[j] * inv;
        }
    }

    // ---- Phase 4: per-row fc logits  RL[r][o] = E[r] . W[pos(r)*5+o] ----
    for (int po = wid; po < 30; po += 8) {
        int pos = po / 5, o = po % 5;
        float wreg[4];
        #pragma unroll
        for (int c = 0; c < 4; ++c) wreg[c] = g_Wt[po * D_ENC + c * 32 + lane];
        #pragma unroll
        for (int i = 0; i < NB; ++i) {
            int r = i * 6 + pos;
            float p = 0.f;
            #pragma unroll
            for (int c = 0; c < 4; ++c)
                p += Es[r * 132 + c * 32 + lane] * wreg[c];
            #pragma unroll
            for (int off = 16; off > 0; off >>= 1)
                p += __shfl_down_sync(0xffffffffu, p, off);
            if (lane == 0) RL[r * 5 + o] = p;
        }
    }
    __syncthreads();

    // ---- Phase 5: combine + gumbel + argmax (order-preserving: skip softmax/TAU) ----
    if (tid < NB) {
        int b = tid;
        int gb = blockIdx.x * NB + b;
        float best = -1e38f;
        int bi = 0;
        #pragma unroll
        for (int o = 0; o < OUTC; ++o) {
            float l = RL[(b * 6) * 5 + o] + fc_b[o];
            #pragma unroll
            for (int j = 0; j < 5; ++j)
                l += Sal[b * 5 + j] * RL[(b * 6 + 1 + j) * 5 + o];
            float uu = u[gb * OUTC + o];
            float g = -logf(-logf(uu + 1e-10f) + 1e-10f);
            l += g;
            if (l > best) { best = l; bi = o; }
        }
        out[gb] = (float)bi;
    }
}

extern "C" void kernel_launch(void* const* d_in, const int* in_sizes, int n_in,
                              void* d_out, int out_size) {
    const float* obs   = (const float*)d_in[0];
    const float* enc_w = (const float*)d_in[1];
    const float* enc_b = (const float*)d_in[2];
    const float* q_w   = (const float*)d_in[3];
    const float* k_w   = (const float*)d_in[4];
    const float* fc_w  = (const float*)d_in[5];
    const float* fc_b  = (const float*)d_in[6];
    const float* u     = (const float*)d_in[7];
    float* out = (float*)d_out;

    cudaFuncSetAttribute(policy_fused_kernel,
                         cudaFuncAttributeMaxDynamicSharedMemorySize,
                         (int)(SMEM_FLOATS * sizeof(float)));

    precompute_kernel<<<D_ENC, D_ENC>>>(q_w, k_w, fc_w);

    int grid = BATCH / NB;  // 4096
    policy_fused_kernel<<<grid, THREADS, SMEM_FLOATS * sizeof(float)>>>(
        obs, enc_w, enc_b, fc_b, u, out);
}

// round 8
// speedup vs baseline: 2.1000x; 1.4245x over previous
#include <cuda_runtime.h>
#include <math.h>

// Problem constants
#define BATCH   32768
#define NAG     6
#define L_IN    225
#define D_ENC   128
#define AD      64
#define OUTC    5

// Tiling
#define NB      16           // batches per CTA
#define ROWS    (NB*NAG)     // 96 encoder rows per CTA
#define KT      16
#define NTILES  14           // 14*16 = 224 full tiles; k=224 handled in acc init
#define THREADS 256
#define RPW     12           // rows per warp (96 / 8 warps)
#define A_STRIDE 20          // As row stride ([row][k]), multiple of 4

typedef unsigned long long ull;

// Precomputed folded weights
__device__ __align__(16) float g_M[D_ENC * D_ENC];   // q_w @ k_w^T
__device__ __align__(16) float g_Wt[30 * D_ENC];     // fc weights, [(pos*5+o)][k]

__device__ __forceinline__ ull pack2(float x) {
    ull r; asm("mov.b64 %0, {%1, %1};" : "=l"(r) : "f"(x)); return r;
}
__device__ __forceinline__ ull packab(float a, float b) {
    ull r; asm("mov.b64 %0, {%1, %2};" : "=l"(r) : "f"(a), "f"(b)); return r;
}
__device__ __forceinline__ void fma2(ull &c, ull a, ull b) {
    asm("fma.rn.f32x2 %0, %1, %2, %0;" : "+l"(c) : "l"(a), "l"(b));
}
__device__ __forceinline__ float2 unpack2(ull v) {
    float2 f; asm("mov.b64 {%0, %1}, %2;" : "=f"(f.x), "=f"(f.y) : "l"(v)); return f;
}
__device__ __forceinline__ unsigned smem_u32(const void* p) {
    return (unsigned)__cvta_generic_to_shared(p);
}
__device__ __forceinline__ void cp4(unsigned dst, const float* src) {
    asm volatile("cp.async.ca.shared.global [%0], [%1], 4;"
                 :: "r"(dst), "l"(src));
}
__device__ __forceinline__ void cp16(unsigned dst, const float* src) {
    asm volatile("cp.async.cg.shared.global [%0], [%1], 16;"
                 :: "r"(dst), "l"(src));
}
__device__ __forceinline__ void cp_commit() {
    asm volatile("cp.async.commit_group;");
}
template <int N>
__device__ __forceinline__ void cp_wait() {
    asm volatile("cp.async.wait_group %0;" :: "n"(N));
}

__global__ void precompute_kernel(const float* __restrict__ q_w,
                                  const float* __restrict__ k_w,
                                  const float* __restrict__ fc_w) {
    int i = blockIdx.x;    // 0..127
    int j = threadIdx.x;   // 0..127
    float s = 0.f;
    #pragma unroll 8
    for (int a = 0; a < AD; ++a) s += q_w[i * AD + a] * k_w[j * AD + a];
    g_M[i * D_ENC + j] = s;
    if (j < 30) {
        int pos = j / 5, o = j % 5;
        float v;
        if (pos == 0) {
            v = 0.f;
            #pragma unroll
            for (int e = 0; e < 5; ++e) v += fc_w[(e * D_ENC + i) * OUTC + o];
        } else {
            v = fc_w[((pos + 4) * D_ENC + i) * OUTC + o];
        }
        g_Wt[j * D_ENC + i] = v;
    }
}

// Shared memory layout (floats):
#define AS_BUF   (ROWS*A_STRIDE)            // 1920 per buffer
#define BS_BUF   (KT*D_ENC)                 // 2048 per buffer
#define OFF_AS   0                          // 2*1920 = 3840
#define OFF_BS   (OFF_AS + 2*AS_BUF)        // 2*2048 = 4096
#define OFF_ES   (OFF_BS + 2*BS_BUF)        // 96*132 = 12672
#define OFF_TS   (OFF_ES + ROWS*132)        // 16*132 = 2112
#define OFF_SAL  (OFF_TS + NB*132)          // 80
#define OFF_RL   (OFF_SAL + NB*5)           // 480
#define SMEM_FLOATS (OFF_RL + ROWS*5)       // 23280 floats = 93120 B

__global__ __launch_bounds__(THREADS, 2)
void policy_fused_kernel(const float* __restrict__ obs,
                         const float* __restrict__ enc_w,
                         const float* __restrict__ enc_b,
                         const float* __restrict__ fc_b,
                         const float* __restrict__ u,
                         float* __restrict__ out) {
    extern __shared__ float sm[];
    float* Es  = sm + OFF_ES;
    float* Ts  = sm + OFF_TS;
    float* Sal = sm + OFF_SAL;
    float* RL  = sm + OFF_RL;

    const int tid  = threadIdx.x;
    const int wid  = tid >> 5;   // warp id (0..7)
    const int lane = tid & 31;
    const int r0   = wid * RPW;  // this warp's 12 encoder rows

    // Per-thread tile-load indices
    const int la_k  = tid & 15;              // A: k within tile
    const int lb_n4 = (tid & 31) * 4;        // B: col group

    const float* obsBase = obs + (size_t)blockIdx.x * NB * NAG * L_IN;

    // cp.async issue for one FULL tile (no predication; tiles 0..13 all in-bounds)
    auto issue_tile = [&](int tile, int stage) {
        const int k0 = tile * KT;
        unsigned as_s = smem_u32(sm + OFF_AS + stage * AS_BUF);
        unsigned bs_s = smem_u32(sm + OFF_BS + stage * BS_BUF);
        // A: 96 rows x 16 k = 1536 scalars, 6 per thread
        #pragma unroll
        for (int t = 0; t < 6; ++t) {
            int r = (tid + 256 * t) >> 4;
            cp4(as_s + (unsigned)(r * A_STRIDE + la_k) * 4u,
                obsBase + r * L_IN + k0 + la_k);
        }
        // B: 16 x 128 = 512 float4s, 2 per thread
        #pragma unroll
        for (int t = 0; t < 2; ++t) {
            int kk = (tid + 256 * t) >> 5;
            cp16(bs_s + (unsigned)(kk * D_ENC + lb_n4) * 4u,
                 enc_w + (k0 + kk) * D_ENC + lb_n4);
        }
        cp_commit();
    };

    issue_tile(0, 0);

    // ---- Phase 1: E = relu(obs @ enc_w + b). Init acc with k=224 rank-1 term ----
    ull acc[RPW][2];
    {
        const float4 bt = *reinterpret_cast<const float4*>(&enc_w[224 * D_ENC + lane * 4]);
        const ull bt0 = packab(bt.x, bt.y);
        const ull bt1 = packab(bt.z, bt.w);
        #pragma unroll
        for (int r = 0; r < RPW; ++r) {
            ull a2 = pack2(__ldg(&obsBase[(r0 + r) * L_IN + 224]));  // warp-broadcast
            acc[r][0] = 0ull; acc[r][1] = 0ull;
            fma2(acc[r][0], a2, bt0);
            fma2(acc[r][1], a2, bt1);
        }
    }

    for (int tile = 0; tile < NTILES; ++tile) {
        const int cur = tile & 1;
        if (tile + 1 < NTILES) {
            issue_tile(tile + 1, 1 - cur);
            cp_wait<1>();
        } else {
            cp_wait<0>();
        }
        __syncthreads();

        const float* Asc = sm + OFF_AS + cur * AS_BUF;
        const float* Bsc = sm + OFF_BS + cur * BS_BUF;

        #pragma unroll
        for (int c4 = 0; c4 < 4; ++c4) {
            float4 a4[RPW];
            #pragma unroll
            for (int r = 0; r < RPW; ++r)
                a4[r] = *reinterpret_cast<const float4*>(&Asc[(r0 + r) * A_STRIDE + c4 * 4]);
            #pragma unroll
            for (int kk = 0; kk < 4; ++kk) {
                const float4 bf = *reinterpret_cast<const float4*>(&Bsc[(c4 * 4 + kk) * D_ENC + lane * 4]);
                const ull bv0 = packab(bf.x, bf.y);
                const ull bv1 = packab(bf.z, bf.w);
                #pragma unroll
                for (int r = 0; r < RPW; ++r) {
                    ull a2 = pack2(reinterpret_cast<const float*>(&a4[r])[kk]);
                    fma2(acc[r][0], a2, bv0);
                    fma2(acc[r][1], a2, bv1);
                }
            }
        }
        __syncthreads();
    }

    // Epilogue: bias + relu -> Es
    {
        float4 bb = *reinterpret_cast<const float4*>(&enc_b[lane * 4]);
        #pragma unroll
        for (int r = 0; r < RPW; ++r) {
            float2 f0 = unpack2(acc[r][0]);
            float2 f1 = unpack2(acc[r][1]);
            float4 o;
            o.x = fmaxf(f0.x + bb.x, 0.f);
            o.y = fmaxf(f0.y + bb.y, 0.f);
            o.z = fmaxf(f1.x + bb.z, 0.f);
            o.w = fmaxf(f1.y + bb.w, 0.f);
            *reinterpret_cast<float4*>(&Es[(r0 + r) * 132 + lane * 4]) = o;
        }
    }
    __syncthreads();

    // ---- Phase 2: T = E0 @ M (16x128, K=128), scaled by 1/8 ----
    {
        float* Bs0 = sm + OFF_BS;
        const int b0 = wid;        // batches wid and wid+8
        const int b1 = wid + 8;
        ull acc2[2][2] = {{0ull, 0ull}, {0ull, 0ull}};
        for (int k0 = 0; k0 < D_ENC; k0 += KT) {
            #pragma unroll
            for (int t = 0; t < 2; ++t) {
                int fi = tid + THREADS * t;
                int kk = fi >> 5;
                int n4 = (fi & 31) * 4;
                *reinterpret_cast<float4*>(&Bs0[kk * D_ENC + n4]) =
                    *reinterpret_cast<const float4*>(&g_M[(k0 + kk) * D_ENC + n4]);
            }
            __syncthreads();
            #pragma unroll
            for (int kk = 0; kk < KT; ++kk) {
                const float4 bf = *reinterpret_cast<const float4*>(&Bs0[kk * D_ENC + lane * 4]);
                const ull bv0 = packab(bf.x, bf.y);
                const ull bv1 = packab(bf.z, bf.w);
                ull av0 = pack2(Es[(b0 * 6) * 132 + k0 + kk]);
                ull av1 = pack2(Es[(b1 * 6) * 132 + k0 + kk]);
                fma2(acc2[0][0], av0, bv0);
                fma2(acc2[0][1], av0, bv1);
                fma2(acc2[1][0], av1, bv0);
                fma2(acc2[1][1], av1, bv1);
            }
            __syncthreads();
        }
        #pragma unroll
        for (int s = 0; s < 2; ++s) {
            int b = (s == 0) ? b0 : b1;
            float2 f0 = unpack2(acc2[s][0]);
            float2 f1 = unpack2(acc2[s][1]);
            float4 o; o.x = f0.x * 0.125f; o.y = f0.y * 0.125f;
            o.z = f1.x * 0.125f; o.w = f1.y * 0.125f;
            *reinterpret_cast<float4*>(&Ts[b * 132 + lane * 4]) = o;
        }
    }
    __syncthreads();

    // ---- Phase 3: scores_j = T[b] . E[vis_j], softmax over 5 ----
    #pragma unroll
    for (int it = 0; it < 2; ++it) {
        int b = wid + 8 * it;
        float part[5] = {0.f, 0.f, 0.f, 0.f, 0.f};
        #pragma unroll
        for (int c = 0; c < 4; ++c) {
            int kk = c * 32 + lane;
            float tv = Ts[b * 132 + kk];
            #pragma unroll
            for (int j = 0; j < 5; ++j)
                part[j] += tv * Es[(b * 6 + 1 + j) * 132 + kk];
        }
        #pragma unroll
        for (int off = 16; off > 0; off >>= 1)
            #pragma unroll
            for (int j = 0; j < 5; ++j)
                part[j] += __shfl_down_sync(0xffffffffu, part[j], off);
        if (lane == 0) {
            float m = part[0];
            #pragma unroll
            for (int j = 1; j < 5; ++j) m = fmaxf(m, part[j]);
            float ex[5], s = 0.f;
            #pragma unroll
            for (int j = 0; j < 5; ++j) { ex[j] = expf(part[j] - m); s += ex[j]; }
            float inv = 1.f / s;
            #pragma unroll
            for (int j = 0; j < 5; ++j) Sal[b * 5 + j] = ex[j] * inv;
        }
    }

    // ---- Phase 4: per-row fc logits  RL[r][o] = E[r] . W[pos(r)*5+o] ----
    for (int po = wid; po < 30; po += 8) {
        int pos = po / 5, o = po % 5;
        float wreg[4];
        #pragma unroll
        for (int c = 0; c < 4; ++c) wreg[c] = g_Wt[po * D_ENC + c * 32 + lane];
        #pragma unroll
        for (int i = 0; i < NB; ++i) {
            int r = i * 6 + pos;
            float p = 0.f;
            #pragma unroll
            for (int c = 0; c < 4; ++c)
                p += Es[r * 132 + c * 32 + lane] * wreg[c];
            #pragma unroll
            for (int off = 16; off > 0; off >>= 1)
                p += __shfl_down_sync(0xffffffffu, p, off);
            if (lane == 0) RL[r * 5 + o] = p;
        }
    }
    __syncthreads();

    // ---- Phase 5: combine + gumbel + argmax ----
    if (tid < NB) {
        int b = tid;
        int gb = blockIdx.x * NB + b;
        float best = -1e38f;
        int bi = 0;
        #pragma unroll
        for (int o = 0; o < OUTC; ++o) {
            float l = RL[(b * 6) * 5 + o] + fc_b[o];
            #pragma unroll
            for (int j = 0; j < 5; ++j)
                l += Sal[b * 5 + j] * RL[(b * 6 + 1 + j) * 5 + o];
            float uu = u[gb * OUTC + o];
            float g = -logf(-logf(uu + 1e-10f) + 1e-10f);
            l += g;
            if (l > best) { best = l; bi = o; }
        }
        out[gb] = (float)bi;
    }
}

extern "C" void kernel_launch(void* const* d_in, const int* in_sizes, int n_in,
                              void* d_out, int out_size) {
    const float* obs   = (const float*)d_in[0];
    const float* enc_w = (const float*)d_in[1];
    const float* enc_b = (const float*)d_in[2];
    const float* q_w   = (const float*)d_in[3];
    const float* k_w   = (const float*)d_in[4];
    const float* fc_w  = (const float*)d_in[5];
    const float* fc_b  = (const float*)d_in[6];
    const float* u     = (const float*)d_in[7];
    float* out = (float*)d_out;

    cudaFuncSetAttribute(policy_fused_kernel,
                         cudaFuncAttributeMaxDynamicSharedMemorySize,
                         (int)(SMEM_FLOATS * sizeof(float)));

    precompute_kernel<<<D_ENC, D_ENC>>>(q_w, k_w, fc_w);

    int grid = BATCH / NB;  // 2048
    policy_fused_kernel<<<grid, THREADS, SMEM_FLOATS * sizeof(float)>>>(
        obs, enc_w, enc_b, fc_b, u, out);
}